// round 1
// baseline (speedup 1.0000x reference)
#include <cuda_runtime.h>
#include <cstdint>
#include <math.h>

#define B_  16
#define S_  4096
#define D_  512
#define DH_ 256
#define M_  (B_ * S_)   // 65536

// Scratch (device globals: allocation-free per harness rules)
__device__ float g_h[(size_t)M_ * DH_];    // 64 MB intermediate h
__device__ float g_cv[(size_t)M_ * D_];    // 134 MB conditional variance

// ---------------------------------------------------------------------------
// GARCH(1,1) scan: one thread per (b, d); serial over S with 1-FMA dep chain.
// ---------------------------------------------------------------------------
__global__ void __launch_bounds__(256) garch_kernel(
    const float* __restrict__ ret,
    const float* __restrict__ pa, const float* __restrict__ pb,
    const float* __restrict__ pw)
{
    int t = blockIdx.x * blockDim.x + threadIdx.x;   // 0..8191
    float alpha = pa[0], beta = pb[0], omega = pw[0];
    int b = t >> 9;
    int d = t & (D_ - 1);
    const float* rp = ret + (size_t)b * S_ * D_ + d;
    float* cp = g_cv + (size_t)b * S_ * D_ + d;
    float cv = 0.01f;
    cp[0] = cv;
#pragma unroll 8
    for (int s = 1; s < S_; ++s) {
        float r = rp[(size_t)(s - 1) * D_];
        cv = fmaf(beta, cv, fmaf(alpha, r * r, omega));
        cp[(size_t)s * D_] = cv;
    }
}

// ---------------------------------------------------------------------------
// TF32 tensor-core GEMM: 128x128 block tile, BK=16, 4 warps (64x64 each),
// cp.async double buffering, conflict-free padded smem.
// ---------------------------------------------------------------------------
#define BM 128
#define BN 128
#define BK 16
#define ASTR 20    // As row stride (floats): banks (20*gid + tig) % 32 all distinct
#define BSTR 136   // Bs row stride (floats): banks (8*k + n) % 32 all distinct

__device__ __forceinline__ uint32_t f2tf(float f) {
    uint32_t r;
    asm("cvt.rna.tf32.f32 %0, %1;" : "=r"(r) : "f"(f));
    return r;
}

__device__ __forceinline__ void cp_async16(void* dst_smem, const void* src_g) {
    uint32_t d32 = (uint32_t)__cvta_generic_to_shared(dst_smem);
    asm volatile("cp.async.cg.shared.global [%0], [%1], 16;" :: "r"(d32), "l"(src_g));
}

__device__ __forceinline__ float softplus_f(float z) {
    // matches jax.nn.softplus: max(z,0) + log1p(exp(-|z|))
    return fmaxf(z, 0.f) + log1pf(expf(-fabsf(z)));
}

// EPI==0: C = relu(A@B + bias)            (h = relu(x@W1+b1))
// EPI==1: C = softplus(A@B + bias) * CV   (out)
template <int EPI>
__device__ __forceinline__ void gemm_body(
    const float* __restrict__ A, const float* __restrict__ Bw,
    const float* __restrict__ bias, const float* __restrict__ CV,
    float* __restrict__ C, const int N, const int K)
{
    __shared__ float As[2][BM][ASTR];
    __shared__ float Bs[2][BK][BSTR];

    const int tid  = threadIdx.x;
    const int lane = tid & 31;
    const int warp = tid >> 5;
    const int wm   = (warp >> 1) * 64;   // 2x2 warp grid
    const int wn   = (warp & 1) * 64;
    const int gid  = lane >> 2;
    const int tig  = lane & 3;
    const int bm0  = blockIdx.y * BM;
    const int bn0  = blockIdx.x * BN;

    float acc[4][8][4];
#pragma unroll
    for (int mt = 0; mt < 4; ++mt)
#pragma unroll
        for (int nt = 0; nt < 8; ++nt)
#pragma unroll
            for (int i = 0; i < 4; ++i) acc[mt][nt][i] = 0.f;

    auto load_tiles = [&](int kt, int buf) {
        const float* Ag = A + (size_t)bm0 * K + kt * BK;
#pragma unroll
        for (int i = 0; i < 4; ++i) {
            int idx = tid + i * 128;          // 512 float4s for 128x16 tile
            int r = idx >> 2, cq = (idx & 3) * 4;
            cp_async16(&As[buf][r][cq], Ag + (size_t)r * K + cq);
        }
        const float* Bg = Bw + (size_t)(kt * BK) * N + bn0;
#pragma unroll
        for (int i = 0; i < 4; ++i) {
            int idx = tid + i * 128;          // 512 float4s for 16x128 tile
            int r = idx >> 5, cq = (idx & 31) * 4;
            cp_async16(&Bs[buf][r][cq], Bg + (size_t)r * N + cq);
        }
        asm volatile("cp.async.commit_group;" ::: "memory");
    };

    const int nk = K / BK;
    load_tiles(0, 0);

    for (int kt = 0; kt < nk; ++kt) {
        asm volatile("cp.async.wait_group 0;" ::: "memory");
        __syncthreads();                        // tile kt visible; frees buf^1
        const int buf = kt & 1;
        if (kt + 1 < nk) load_tiles(kt + 1, buf ^ 1);

#pragma unroll
        for (int ks = 0; ks < 2; ++ks) {        // two k8 sub-steps
            const int k0 = ks * 8;
            uint32_t af[4][4], bf[8][2];
#pragma unroll
            for (int mt = 0; mt < 4; ++mt) {
                int r = wm + mt * 16 + gid;
                af[mt][0] = f2tf(As[buf][r    ][k0 + tig]);
                af[mt][1] = f2tf(As[buf][r + 8][k0 + tig]);
                af[mt][2] = f2tf(As[buf][r    ][k0 + tig + 4]);
                af[mt][3] = f2tf(As[buf][r + 8][k0 + tig + 4]);
            }
#pragma unroll
            for (int nt = 0; nt < 8; ++nt) {
                int c = wn + nt * 8 + gid;
                bf[nt][0] = f2tf(Bs[buf][k0 + tig    ][c]);
                bf[nt][1] = f2tf(Bs[buf][k0 + tig + 4][c]);
            }
#pragma unroll
            for (int mt = 0; mt < 4; ++mt)
#pragma unroll
                for (int nt = 0; nt < 8; ++nt)
                    asm volatile(
                        "mma.sync.aligned.m16n8k8.row.col.f32.tf32.tf32.f32 "
                        "{%0,%1,%2,%3},{%4,%5,%6,%7},{%8,%9},{%0,%1,%2,%3};"
                        : "+f"(acc[mt][nt][0]), "+f"(acc[mt][nt][1]),
                          "+f"(acc[mt][nt][2]), "+f"(acc[mt][nt][3])
                        : "r"(af[mt][0]), "r"(af[mt][1]),
                          "r"(af[mt][2]), "r"(af[mt][3]),
                          "r"(bf[nt][0]), "r"(bf[nt][1]));
        }
    }

    // Epilogue
#pragma unroll
    for (int mt = 0; mt < 4; ++mt) {
#pragma unroll
        for (int i = 0; i < 2; ++i) {
            const int row = bm0 + wm + mt * 16 + gid + i * 8;
#pragma unroll
            for (int nt = 0; nt < 8; ++nt) {
                const int col = bn0 + wn + nt * 8 + 2 * tig;
                float v0 = acc[mt][nt][2 * i + 0] + bias[col];
                float v1 = acc[mt][nt][2 * i + 1] + bias[col + 1];
                if (EPI == 0) {
                    v0 = fmaxf(v0, 0.f);
                    v1 = fmaxf(v1, 0.f);
                } else {
                    v0 = softplus_f(v0) * CV[(size_t)row * N + col];
                    v1 = softplus_f(v1) * CV[(size_t)row * N + col + 1];
                }
                *(float2*)(C + (size_t)row * N + col) = make_float2(v0, v1);
            }
        }
    }
}

__global__ void __launch_bounds__(128) gemm1_kernel(
    const float* __restrict__ x, const float* __restrict__ W1,
    const float* __restrict__ b1)
{
    gemm_body<0>(x, W1, b1, nullptr, g_h, DH_, D_);
}

__global__ void __launch_bounds__(128) gemm2_kernel(
    const float* __restrict__ W2, const float* __restrict__ b2,
    float* __restrict__ out)
{
    gemm_body<1>(g_h, W2, b2, g_cv, out, D_, DH_);
}

// ---------------------------------------------------------------------------
extern "C" void kernel_launch(void* const* d_in, const int* in_sizes, int n_in,
                              void* d_out, int out_size)
{
    const float* x   = (const float*)d_in[0];
    const float* ret = (const float*)d_in[1];
    const float* al  = (const float*)d_in[2];
    const float* be  = (const float*)d_in[3];
    const float* om  = (const float*)d_in[4];
    const float* W1  = (const float*)d_in[5];
    const float* b1  = (const float*)d_in[6];
    const float* W2  = (const float*)d_in[7];
    const float* b2  = (const float*)d_in[8];
    float* out = (float*)d_out;

    garch_kernel<<<(B_ * D_) / 256, 256>>>(ret, al, be, om);
    gemm1_kernel<<<dim3(DH_ / BN, M_ / BM), 128>>>(x, W1, b1);
    gemm2_kernel<<<dim3(D_  / BN, M_ / BM), 128>>>(W2, b2, out);
}

// round 2
// speedup vs baseline: 1.8155x; 1.8155x over previous
#include <cuda_runtime.h>
#include <cstdint>
#include <math.h>

#define B_  16
#define S_  4096
#define D_  512
#define DH_ 256
#define M_  (B_ * S_)   // 65536
#define CL_ 128         // GARCH chunk length
#define NC_ 32          // chunks per series (S_/CL_)

// Scratch (device globals: allocation-free per harness rules)
__device__ float g_h[(size_t)M_ * DH_];        // 64 MB intermediate h
__device__ float g_cv[(size_t)M_ * D_];        // 134 MB PARTIAL cond-var (zero carry-in)
__device__ float g_carry[B_ * NC_ * D_];       // 1 MB chunk carry terms
__device__ float g_cvs[B_ * NC_ * D_];         // 1 MB chunk start values

// ---------------------------------------------------------------------------
// GARCH pass A: per (b, chunk, d) compute partial cv (carry-in = 0) and the
// chunk carry term B_c.  cv[t] = u[t-1] + beta*cv[t-1], u[s]=omega+alpha*r[s]^2
// ---------------------------------------------------------------------------
__global__ void __launch_bounds__(256) garch_partial_kernel(
    const float* __restrict__ ret,
    const float* __restrict__ pa, const float* __restrict__ pb,
    const float* __restrict__ pw)
{
    const int g = blockIdx.x;                 // 1024 blocks
    const int d = ((g & 1) << 8) + threadIdx.x;
    const int c = (g >> 1) & (NC_ - 1);
    const int b = g >> 6;
    const float alpha = pa[0], beta = pb[0], omega = pw[0];

    const size_t base = ((size_t)b * S_ + (size_t)c * CL_) * D_ + d;
    const float* rp = ret + base;
    float* cp = g_cv + base;

    float p = 0.f;
    cp[0] = 0.f;
#pragma unroll 8
    for (int k = 1; k < CL_; ++k) {
        float r = rp[(size_t)(k - 1) * D_];
        p = fmaf(beta, p, fmaf(alpha, r * r, omega));
        cp[(size_t)k * D_] = p;
    }
    float rl = rp[(size_t)(CL_ - 1) * D_];
    float Bc = fmaf(beta, p, fmaf(alpha, rl * rl, omega));
    g_carry[(((b << 5) + c) << 9) + d] = Bc;
}

// ---------------------------------------------------------------------------
// GARCH pass B: serial scan over the 32 chunk carries per (b, d).
// cvs[c] = beta^CL * cvs[c-1] + carry[c-1];  cvs[0] = 0.01
// ---------------------------------------------------------------------------
__global__ void __launch_bounds__(256) garch_scan_kernel(
    const float* __restrict__ pb)
{
    const int t = blockIdx.x * 256 + threadIdx.x;   // 0..8191
    const int b = t >> 9;
    const int d = t & (D_ - 1);
    const float beta = pb[0];
    float A = 1.f;
#pragma unroll
    for (int i = 0; i < CL_; ++i) A *= beta;        // beta^128 (~4e-13)

    float cvs = 0.01f;
#pragma unroll 4
    for (int c = 0; c < NC_; ++c) {
        const int idx = (((b << 5) + c) << 9) + d;
        g_cvs[idx] = cvs;
        cvs = fmaf(A, cvs, g_carry[idx]);
    }
}

// ---------------------------------------------------------------------------
// TF32 tensor-core GEMM: 128x128 block tile, BK=16, 8 warps (64x32 each),
// cp.async double buffering, conflict-free padded smem.
// ---------------------------------------------------------------------------
#define BM 128
#define BN 128
#define BK 16
#define ASTR 20    // As row stride (floats): (20*gid + tig) % 32 all distinct
#define BSTR 136   // Bs row stride (floats): (8*tig + gid) % 32 all distinct

__device__ __forceinline__ uint32_t f2tf(float f) {
    uint32_t r;
    asm("cvt.rna.tf32.f32 %0, %1;" : "=r"(r) : "f"(f));
    return r;
}

__device__ __forceinline__ void cp_async16(void* dst_smem, const void* src_g) {
    uint32_t d32 = (uint32_t)__cvta_generic_to_shared(dst_smem);
    asm volatile("cp.async.cg.shared.global [%0], [%1], 16;" :: "r"(d32), "l"(src_g));
}

__device__ __forceinline__ float softplus_f(float z) {
    return fmaxf(z, 0.f) + log1pf(expf(-fabsf(z)));
}

// EPI==0: C = relu(A@B + bias)
// EPI==1: C = softplus(A@B + bias) * (CVpart + beta^(s%128) * CVS[b,chunk,:])
template <int EPI>
__device__ __forceinline__ void gemm_body(
    const float* __restrict__ A, const float* __restrict__ Bw,
    const float* __restrict__ bias,
    const float* __restrict__ CV, const float* __restrict__ CVS,
    const float* __restrict__ pbeta,
    float* __restrict__ C, const int N, const int K)
{
    __shared__ float As[2][BM][ASTR];
    __shared__ float Bs[2][BK][BSTR];
    __shared__ float bp[CL_];

    const int tid  = threadIdx.x;
    const int lane = tid & 31;
    const int warp = tid >> 5;
    const int wm   = (warp >> 2) * 64;   // 2x4 warp grid, 64x32 per warp
    const int wn   = (warp & 3) * 32;
    const int gid  = lane >> 2;
    const int tig  = lane & 3;
    const int bm0  = blockIdx.y * BM;
    const int bn0  = blockIdx.x * BN;

    if (EPI == 1 && tid < CL_) bp[tid] = powf(pbeta[0], (float)tid);

    float acc[4][4][4];
#pragma unroll
    for (int mt = 0; mt < 4; ++mt)
#pragma unroll
        for (int nt = 0; nt < 4; ++nt)
#pragma unroll
            for (int i = 0; i < 4; ++i) acc[mt][nt][i] = 0.f;

    auto load_tiles = [&](int kt, int buf) {
        const float* Ag = A + (size_t)bm0 * K + kt * BK;
#pragma unroll
        for (int i = 0; i < 2; ++i) {
            int idx = tid + i * 256;          // 512 float4s for 128x16 tile
            int r = idx >> 2, cq = (idx & 3) * 4;
            cp_async16(&As[buf][r][cq], Ag + (size_t)r * K + cq);
        }
        const float* Bg = Bw + (size_t)(kt * BK) * N + bn0;
#pragma unroll
        for (int i = 0; i < 2; ++i) {
            int idx = tid + i * 256;          // 512 float4s for 16x128 tile
            int r = idx >> 5, cq = (idx & 31) * 4;
            cp_async16(&Bs[buf][r][cq], Bg + (size_t)r * N + cq);
        }
        asm volatile("cp.async.commit_group;" ::: "memory");
    };

    const int nk = K / BK;
    load_tiles(0, 0);

    for (int kt = 0; kt < nk; ++kt) {
        asm volatile("cp.async.wait_group 0;" ::: "memory");
        __syncthreads();
        const int buf = kt & 1;
        if (kt + 1 < nk) load_tiles(kt + 1, buf ^ 1);

#pragma unroll
        for (int ks = 0; ks < 2; ++ks) {
            const int k0 = ks * 8;
            uint32_t af[4][4], bf[4][2];
#pragma unroll
            for (int mt = 0; mt < 4; ++mt) {
                int r = wm + mt * 16 + gid;
                af[mt][0] = f2tf(As[buf][r    ][k0 + tig]);
                af[mt][1] = f2tf(As[buf][r + 8][k0 + tig]);
                af[mt][2] = f2tf(As[buf][r    ][k0 + tig + 4]);
                af[mt][3] = f2tf(As[buf][r + 8][k0 + tig + 4]);
            }
#pragma unroll
            for (int nt = 0; nt < 4; ++nt) {
                int c = wn + nt * 8 + gid;
                bf[nt][0] = f2tf(Bs[buf][k0 + tig    ][c]);
                bf[nt][1] = f2tf(Bs[buf][k0 + tig + 4][c]);
            }
#pragma unroll
            for (int mt = 0; mt < 4; ++mt)
#pragma unroll
                for (int nt = 0; nt < 4; ++nt)
                    asm volatile(
                        "mma.sync.aligned.m16n8k8.row.col.f32.tf32.tf32.f32 "
                        "{%0,%1,%2,%3},{%4,%5,%6,%7},{%8,%9},{%0,%1,%2,%3};"
                        : "+f"(acc[mt][nt][0]), "+f"(acc[mt][nt][1]),
                          "+f"(acc[mt][nt][2]), "+f"(acc[mt][nt][3])
                        : "r"(af[mt][0]), "r"(af[mt][1]),
                          "r"(af[mt][2]), "r"(af[mt][3]),
                          "r"(bf[nt][0]), "r"(bf[nt][1]));
        }
    }

    // Epilogue
#pragma unroll
    for (int mt = 0; mt < 4; ++mt) {
#pragma unroll
        for (int i = 0; i < 2; ++i) {
            const int row = bm0 + wm + mt * 16 + gid + i * 8;
            float bpk = 0.f;
            size_t cvsbase = 0;
            if (EPI == 1) {
                bpk = bp[row & (CL_ - 1)];
                cvsbase = (size_t)((((row >> 12) << 5) + ((row >> 7) & 31)) << 9);
            }
#pragma unroll
            for (int nt = 0; nt < 4; ++nt) {
                const int col = bn0 + wn + nt * 8 + 2 * tig;
                float v0 = acc[mt][nt][2 * i + 0] + bias[col];
                float v1 = acc[mt][nt][2 * i + 1] + bias[col + 1];
                if (EPI == 0) {
                    v0 = fmaxf(v0, 0.f);
                    v1 = fmaxf(v1, 0.f);
                } else {
                    float cv0 = CV[(size_t)row * N + col]     + bpk * CVS[cvsbase + col];
                    float cv1 = CV[(size_t)row * N + col + 1] + bpk * CVS[cvsbase + col + 1];
                    v0 = softplus_f(v0) * cv0;
                    v1 = softplus_f(v1) * cv1;
                }
                *(float2*)(C + (size_t)row * N + col) = make_float2(v0, v1);
            }
        }
    }
}

__global__ void __launch_bounds__(256, 2) gemm1_kernel(
    const float* __restrict__ x, const float* __restrict__ W1,
    const float* __restrict__ b1)
{
    gemm_body<0>(x, W1, b1, nullptr, nullptr, nullptr, g_h, DH_, D_);
}

__global__ void __launch_bounds__(256, 2) gemm2_kernel(
    const float* __restrict__ W2, const float* __restrict__ b2,
    const float* __restrict__ pb, float* __restrict__ out)
{
    gemm_body<1>(g_h, W2, b2, g_cv, g_cvs, pb, out, D_, DH_);
}

// ---------------------------------------------------------------------------
extern "C" void kernel_launch(void* const* d_in, const int* in_sizes, int n_in,
                              void* d_out, int out_size)
{
    const float* x   = (const float*)d_in[0];
    const float* ret = (const float*)d_in[1];
    const float* al  = (const float*)d_in[2];
    const float* be  = (const float*)d_in[3];
    const float* om  = (const float*)d_in[4];
    const float* W1  = (const float*)d_in[5];
    const float* b1  = (const float*)d_in[6];
    const float* W2  = (const float*)d_in[7];
    const float* b2  = (const float*)d_in[8];
    float* out = (float*)d_out;

    garch_partial_kernel<<<B_ * NC_ * (D_ / 256), 256>>>(ret, al, be, om);
    garch_scan_kernel<<<(B_ * D_) / 256, 256>>>(be);
    gemm1_kernel<<<dim3(DH_ / BN, M_ / BM), 256>>>(x, W1, b1);
    gemm2_kernel<<<dim3(D_  / BN, M_ / BM), 256>>>(W2, b2, be, out);
}